// round 2
// baseline (speedup 1.0000x reference)
#include <cuda_runtime.h>
#include <cstddef>

#define NPTS 10000
#define NB 16
#define BN_EPS 1e-5f

// ---------------- static device scratch (allocation-free) ----------------
__device__ float g_bufA[NB * 64 * NPTS];
__device__ float g_bufB[NB * 128 * NPTS];
__device__ float g_y5[NB * 256 * NPTS];
__device__ float g_bn[5][2][256];
__device__ float g_r[NB * 256];
__device__ float g_m[256];
__device__ float g_Spart[4 * NB * 256 * 256];
__device__ float g_nrm[NB];
__device__ float g_Y[NB * 256 * 256];
__device__ float g_Z[NB * 256 * 256];
__device__ float g_P[NB * 256 * 256];
__device__ float g_Y2[NB * 256 * 256];
__device__ float g_Z2[NB * 256 * 256];
__device__ float g_part[16 * 256 * NB];

// ---------------- layer 0: 3 -> 64 raw ----------------
__global__ void k_layer0(const float* __restrict__ pts, const float* __restrict__ W0,
                         float* __restrict__ y) {
    __shared__ float w[192];
    int t = threadIdx.x;
    if (t < 192) w[t] = W0[t];
    __syncthreads();
    int b = blockIdx.y;
    int n = blockIdx.x * 256 + t;
    if (n >= NPTS) return;
    const float* p = pts + ((size_t)b * NPTS + n) * 3;
    float p0 = p[0], p1 = p[1], p2 = p[2];
    float* yo = y + (size_t)b * 64 * NPTS + n;
#pragma unroll
    for (int o = 0; o < 64; ++o)
        yo[(size_t)o * NPTS] = w[o * 3] * p0 + w[o * 3 + 1] * p1 + w[o * 3 + 2] * p2;
}

// ---------------- BN stats over B*N -> per-channel scale/shift ----------------
__global__ void k_stats(const float* __restrict__ y, int C,
                        const float* __restrict__ gam, const float* __restrict__ bet,
                        float* __restrict__ bnout) {
    int c = blockIdx.x, t = threadIdx.x;
    float s = 0.f, s2 = 0.f;
    for (int b = 0; b < NB; ++b) {
        const float* p = y + ((size_t)b * C + c) * NPTS;
        for (int n = t; n < NPTS; n += 256) { float v = p[n]; s += v; s2 += v * v; }
    }
    __shared__ float r1[256], r2[256];
    r1[t] = s; r2[t] = s2; __syncthreads();
    for (int st = 128; st > 0; st >>= 1) {
        if (t < st) { r1[t] += r1[t + st]; r2[t] += r2[t + st]; }
        __syncthreads();
    }
    if (t == 0) {
        float inv = 1.f / (NB * (float)NPTS);
        float mu = r1[0] * inv;
        float var = r2[0] * inv - mu * mu;
        float rstd = rsqrtf(var + BN_EPS);
        float sc = gam[c] * rstd;
        bnout[c] = sc;
        bnout[256 + c] = bet[c] - mu * sc;
    }
}

// ---------------- y = W @ relu(bn(x)); tile 64o x 128n ----------------
template <int CIN, int COUT>
__global__ void k_layer(const float* __restrict__ x, const float* __restrict__ W,
                        const float* __restrict__ bn, float* __restrict__ y) {
    const int b = blockIdx.y;
    const int n0 = blockIdx.x * 128;
    const int o0 = blockIdx.z * 64;
    __shared__ float xs[16][128];
    __shared__ float ws[16][65];
    const float* scale = bn;
    const float* shift = bn + 256;
    float acc[4][8];
#pragma unroll
    for (int i = 0; i < 4; i++)
#pragma unroll
        for (int j = 0; j < 8; j++) acc[i][j] = 0.f;
    int t = threadIdx.x, tx = t & 15, ty = t >> 4;
    for (int c0 = 0; c0 < CIN; c0 += 16) {
#pragma unroll
        for (int i = 0; i < 8; ++i) {
            int e = t + i * 256; int cc = e >> 7, nn = e & 127;
            int n = n0 + nn; int c = c0 + cc;
            float v = 0.f;
            if (n < NPTS) {
                v = x[((size_t)b * CIN + c) * NPTS + n];
                v = fmaxf(fmaf(v, scale[c], shift[c]), 0.f);
            }
            xs[cc][nn] = v;
        }
#pragma unroll
        for (int i = 0; i < 4; ++i) {
            int e = t + i * 256; int oo = e >> 4, cc = e & 15;
            ws[cc][oo] = W[(size_t)(o0 + oo) * CIN + (c0 + cc)];
        }
        __syncthreads();
#pragma unroll
        for (int cc = 0; cc < 16; ++cc) {
            float a[4];
#pragma unroll
            for (int i = 0; i < 4; i++) a[i] = ws[cc][ty * 4 + i];
            float4 b0 = *(const float4*)&xs[cc][tx * 8];
            float4 b1 = *(const float4*)&xs[cc][tx * 8 + 4];
            float bb[8] = {b0.x, b0.y, b0.z, b0.w, b1.x, b1.y, b1.z, b1.w};
#pragma unroll
            for (int i = 0; i < 4; i++)
#pragma unroll
                for (int j = 0; j < 8; j++) acc[i][j] = fmaf(a[i], bb[j], acc[i][j]);
        }
        __syncthreads();
    }
#pragma unroll
    for (int i = 0; i < 4; i++) {
        int o = o0 + ty * 4 + i;
        float* yp = y + ((size_t)b * COUT + o) * NPTS + n0 + tx * 8;
#pragma unroll
        for (int j = 0; j < 8; j++) {
            int n = n0 + tx * 8 + j;
            if (n < NPTS) yp[j] = acc[i][j];
        }
    }
}

// ---------------- per-batch + global channel means of f=relu(bn(y5)) ----------------
__global__ void k_rowmean(const float* __restrict__ y5, const float* __restrict__ bn,
                          float* __restrict__ r, float* __restrict__ m) {
    int d = blockIdx.x, t = threadIdx.x;
    float sc = bn[d], sh = bn[256 + d];
    __shared__ float red[256];
    float msum = 0.f;
    for (int b = 0; b < NB; ++b) {
        const float* p = y5 + ((size_t)b * 256 + d) * NPTS;
        float s = 0.f;
        for (int n = t; n < NPTS; n += 256) s += fmaxf(fmaf(p[n], sc, sh), 0.f);
        red[t] = s; __syncthreads();
        for (int st = 128; st > 0; st >>= 1) {
            if (t < st) red[t] += red[t + st];
            __syncthreads();
        }
        if (t == 0) { r[b * 256 + d] = red[0] / (float)NPTS; msum += red[0]; }
        __syncthreads();
    }
    if (t == 0) m[d] = msum / (NB * (float)NPTS);
}

// ---------------- SYRK partials, symmetric tile pairs, 4-way n-split ----------------
__global__ void k_syrk(const float* __restrict__ y5, const float* __restrict__ bn,
                       float* __restrict__ Sp) {
    const int b = blockIdx.y, ks = blockIdx.z;
    int ti, tj;
    if (blockIdx.x == 0)      { ti = 0; tj = 0; }
    else if (blockIdx.x == 1) { ti = 0; tj = 1; }
    else                      { ti = 1; tj = 1; }
    const int i0 = ti * 128, j0 = tj * 128;
    const int nstart = ks * 2500, nend = nstart + 2500;
    __shared__ float as[16][132];
    __shared__ float bs[16][132];
    const float* scale = bn;
    const float* shift = bn + 256;
    float acc[8][8];
#pragma unroll
    for (int i = 0; i < 8; i++)
#pragma unroll
        for (int j = 0; j < 8; j++) acc[i][j] = 0.f;
    int t = threadIdx.x, tx = t & 15, ty = t >> 4;
    for (int n0 = nstart; n0 < nend; n0 += 16) {
#pragma unroll
        for (int i = 0; i < 8; ++i) {
            int e = t + i * 256; int ii = e >> 4, kk = e & 15;
            int n = n0 + kk;
            float v = 0.f, v2 = 0.f;
            if (n < nend) {
                int c = i0 + ii;
                v = fmaxf(fmaf(y5[((size_t)b * 256 + c) * NPTS + n], scale[c], shift[c]), 0.f);
                int c2 = j0 + ii;
                v2 = fmaxf(fmaf(y5[((size_t)b * 256 + c2) * NPTS + n], scale[c2], shift[c2]), 0.f);
            }
            as[kk][ii] = v;
            bs[kk][ii] = v2;
        }
        __syncthreads();
#pragma unroll
        for (int kk = 0; kk < 16; ++kk) {
            float4 a0 = *(const float4*)&as[kk][ty * 8];
            float4 a1 = *(const float4*)&as[kk][ty * 8 + 4];
            float4 c0 = *(const float4*)&bs[kk][tx * 8];
            float4 c1 = *(const float4*)&bs[kk][tx * 8 + 4];
            float a[8] = {a0.x, a0.y, a0.z, a0.w, a1.x, a1.y, a1.z, a1.w};
            float bb[8] = {c0.x, c0.y, c0.z, c0.w, c1.x, c1.y, c1.z, c1.w};
#pragma unroll
            for (int i = 0; i < 8; i++)
#pragma unroll
                for (int j = 0; j < 8; j++) acc[i][j] = fmaf(a[i], bb[j], acc[i][j]);
        }
        __syncthreads();
    }
    float* Sb = Sp + ((size_t)ks * NB + b) * 65536;
#pragma unroll
    for (int i = 0; i < 8; i++)
#pragma unroll
        for (int j = 0; j < 8; j++) {
            int ii = i0 + ty * 8 + i, jj = j0 + tx * 8 + j;
            Sb[ii * 256 + jj] = acc[i][j];
            if (ti != tj) Sb[jj * 256 + ii] = acc[i][j];
        }
}

// ---------------- cov assembly + Frobenius norm + NS init ----------------
__global__ void k_cov(const float* __restrict__ Sp, const float* __restrict__ r,
                      const float* __restrict__ m, float* __restrict__ Y,
                      float* __restrict__ Z, float* __restrict__ nrm) {
    int b = blockIdx.x, t = threadIdx.x;
    const float invN = 1.f / (float)NPTS;
    float* Yb = Y + (size_t)b * 65536;
    float* Zb = Z + (size_t)b * 65536;
    const float* rb = r + b * 256;
    float ssq = 0.f;
    for (int e = t; e < 65536; e += 256) {
        int i = e >> 8, j = e & 255;
        float s = 0.f;
        for (int ks = 0; ks < 4; ++ks) s += Sp[((size_t)ks * NB + b) * 65536 + e];
        float c = s * invN - rb[i] * m[j] - m[i] * rb[j] + m[i] * m[j];
        Yb[e] = c;
        ssq += c * c;
        Zb[e] = (i == j) ? 1.f : 0.f;
    }
    __shared__ float red[256];
    __shared__ float snorm;
    red[t] = ssq; __syncthreads();
    for (int st = 128; st > 0; st >>= 1) {
        if (t < st) red[t] += red[t + st];
        __syncthreads();
    }
    if (t == 0) { snorm = sqrtf(red[0]); nrm[b] = snorm; }
    __syncthreads();
    float inv = 1.f / snorm;
    for (int e = t; e < 65536; e += 256) Yb[e] *= inv;
}

// ---------------- batched 256^3 GEMM (tile 128x64), optional P-epilogue ----------------
__global__ void k_bgemm256(const float* __restrict__ A0, const float* __restrict__ B0,
                           float* __restrict__ C0, const float* __restrict__ A1,
                           const float* __restrict__ B1, float* __restrict__ C1,
                           float alpha, int epi) {
    const float* A = A0; const float* Bm = B0; float* C = C0;
    if (blockIdx.z == 1) { A = A1; Bm = B1; C = C1; }
    int b = blockIdx.y;
    A  += (size_t)b * 65536;
    Bm += (size_t)b * 65536;
    C  += (size_t)b * 65536;
    int i0 = (blockIdx.x >> 2) * 128, j0 = (blockIdx.x & 3) * 64;
    __shared__ float as[16][132];
    __shared__ float bsm[16][68];
    float acc[8][4];
#pragma unroll
    for (int i = 0; i < 8; i++)
#pragma unroll
        for (int j = 0; j < 4; j++) acc[i][j] = 0.f;
    int t = threadIdx.x, tx = t & 15, ty = t >> 4;
    for (int c0 = 0; c0 < 256; c0 += 16) {
#pragma unroll
        for (int i = 0; i < 8; ++i) {
            int e = t + i * 256; int ii = e >> 4, kk = e & 15;
            as[kk][ii] = A[(i0 + ii) * 256 + c0 + kk];
        }
#pragma unroll
        for (int i = 0; i < 4; ++i) {
            int e = t + i * 256; int kk = e >> 6, jj = e & 63;
            bsm[kk][jj] = Bm[(c0 + kk) * 256 + j0 + jj];
        }
        __syncthreads();
#pragma unroll
        for (int kk = 0; kk < 16; ++kk) {
            float4 a0 = *(const float4*)&as[kk][ty * 8];
            float4 a1 = *(const float4*)&as[kk][ty * 8 + 4];
            float4 bv = *(const float4*)&bsm[kk][tx * 4];
            float a[8] = {a0.x, a0.y, a0.z, a0.w, a1.x, a1.y, a1.z, a1.w};
            float bb[4] = {bv.x, bv.y, bv.z, bv.w};
#pragma unroll
            for (int i = 0; i < 8; i++)
#pragma unroll
                for (int j = 0; j < 4; j++) acc[i][j] = fmaf(a[i], bb[j], acc[i][j]);
        }
        __syncthreads();
    }
#pragma unroll
    for (int i = 0; i < 8; i++)
#pragma unroll
        for (int j = 0; j < 4; j++) {
            int ii = i0 + ty * 8 + i, jj = j0 + tx * 4 + j;
            float v = acc[i][j];
            if (epi) v = ((ii == jj) ? alpha : 0.f) - (alpha - 1.f) * v;
            C[ii * 256 + jj] = v;
        }
}

// ---------------- FC partials over 4096-k chunks ----------------
__global__ void k_fc(const float* __restrict__ Yfin, const float* __restrict__ nrm,
                     const float* __restrict__ Wfc, float* __restrict__ part) {
    int o0 = blockIdx.x * 16, k0 = blockIdx.y * 4096;
    __shared__ float vs[16][129];
    __shared__ float wsm[16][129];
    __shared__ float sq[16];
    int t = threadIdx.x;
    if (t < 16) sq[t] = sqrtf(nrm[t]);
    __syncthreads();
    int oo = t & 15, bb = t >> 4;
    float acc = 0.f;
    for (int kc = 0; kc < 4096; kc += 128) {
#pragma unroll
        for (int i = 0; i < 8; ++i) {
            int e = t + i * 256; int row = e >> 7, kk = e & 127;
            vs[row][kk]  = sq[row] * Yfin[(size_t)row * 65536 + k0 + kc + kk];
            wsm[row][kk] = Wfc[(size_t)(o0 + row) * 65536 + k0 + kc + kk];
        }
        __syncthreads();
#pragma unroll
        for (int kk = 0; kk < 128; kk++) acc = fmaf(wsm[oo][kk], vs[bb][kk], acc);
        __syncthreads();
    }
    part[((size_t)blockIdx.y * 256 + o0 + oo) * 16 + bb] = acc;
}

// ---------------- finalize: bias + L2 normalize ----------------
__global__ void k_fin(const float* __restrict__ part, const float* __restrict__ bfc,
                      float* __restrict__ out) {
    int b = blockIdx.x, t = threadIdx.x;
    float v = bfc[t];
    for (int ks = 0; ks < 16; ++ks) v += part[((size_t)ks * 256 + t) * 16 + b];
    __shared__ float red[256];
    red[t] = v * v; __syncthreads();
    for (int st = 128; st > 0; st >>= 1) {
        if (t < st) red[t] += red[t + st];
        __syncthreads();
    }
    float nrm = fmaxf(sqrtf(red[0]), 1e-12f);
    out[b * 256 + t] = v / nrm;
}

// ---------------- host driver ----------------
static float* symaddr(const void* sym) {
    void* p = nullptr;
    cudaGetSymbolAddress(&p, sym);
    return (float*)p;
}

extern "C" void kernel_launch(void* const* d_in, const int* in_sizes, int n_in,
                              void* d_out, int out_size) {
    const float* pts = (const float*)d_in[0];
    const float* W[5]; const float* G[5]; const float* Bt[5];
    for (int l = 0; l < 5; ++l) {
        W[l]  = (const float*)d_in[1 + 3 * l];
        G[l]  = (const float*)d_in[2 + 3 * l];
        Bt[l] = (const float*)d_in[3 + 3 * l];
    }
    const float* Wfc = (const float*)d_in[16];
    const float* bfc = (const float*)d_in[17];
    float* out = (float*)d_out;

    float* bufA = symaddr(g_bufA);
    float* bufB = symaddr(g_bufB);
    float* y5   = symaddr(g_y5);
    float* bn   = symaddr(g_bn);
    float* r    = symaddr(g_r);
    float* m    = symaddr(g_m);
    float* Sp   = symaddr(g_Spart);
    float* nrm  = symaddr(g_nrm);
    float* Y    = symaddr(g_Y);
    float* Z    = symaddr(g_Z);
    float* P    = symaddr(g_P);
    float* Y2   = symaddr(g_Y2);
    float* Z2   = symaddr(g_Z2);
    float* part = symaddr(g_part);

    const int NT = (NPTS + 127) / 128;  // 79

    // MLP 3->64->64->64->128->256 with training-mode BN between layers
    k_layer0<<<dim3((NPTS + 255) / 256, NB), 256>>>(pts, W[0], bufA);
    k_stats<<<64, 256>>>(bufA, 64, G[0], Bt[0], bn + 0 * 512);
    k_layer<64, 64><<<dim3(NT, NB, 1), 256>>>(bufA, W[1], bn + 0 * 512, bufB);
    k_stats<<<64, 256>>>(bufB, 64, G[1], Bt[1], bn + 1 * 512);
    k_layer<64, 64><<<dim3(NT, NB, 1), 256>>>(bufB, W[2], bn + 1 * 512, bufA);
    k_stats<<<64, 256>>>(bufA, 64, G[2], Bt[2], bn + 2 * 512);
    k_layer<64, 128><<<dim3(NT, NB, 2), 256>>>(bufA, W[3], bn + 2 * 512, bufB);
    k_stats<<<128, 256>>>(bufB, 128, G[3], Bt[3], bn + 3 * 512);
    k_layer<128, 256><<<dim3(NT, NB, 4), 256>>>(bufB, W[4], bn + 3 * 512, y5);
    k_stats<<<256, 256>>>(y5, 256, G[4], Bt[4], bn + 4 * 512);

    // second-order pooling
    k_rowmean<<<256, 256>>>(y5, bn + 4 * 512, r, m);
    k_syrk<<<dim3(3, NB, 4), 256>>>(y5, bn + 4 * 512, Sp);
    k_cov<<<NB, 256>>>(Sp, r, m, Y, Z, nrm);

    // Newton-Schulz coupled iteration: 16 accelerated + 6 standard
    float* curY = Y; float* curZ = Z; float* nY = Y2; float* nZ = Z2;
    for (int it = 0; it < 22; ++it) {
        float alpha = (it < 16) ? 1.9f : 1.5f;
        k_bgemm256<<<dim3(8, NB, 1), 256>>>(curZ, curY, P, curZ, curY, P, alpha, 1);
        k_bgemm256<<<dim3(8, NB, 2), 256>>>(curY, P, nY, P, curZ, nZ, 0.f, 0);
        float* tY = curY; curY = nY; nY = tY;
        float* tZ = curZ; curZ = nZ; nZ = tZ;
    }

    // FC + L2 normalize
    k_fc<<<dim3(16, 16), 256>>>(curY, nrm, Wfc, part);
    k_fin<<<NB, 256>>>(part, bfc, out);
}

// round 5
// speedup vs baseline: 1.1595x; 1.1595x over previous
#include <cuda_runtime.h>
#include <cstddef>

#define NPTS 10000
#define NB 16
#define BN_EPS 1e-5f

// ---------------- static device scratch (allocation-free) ----------------
__device__ float g_bufA[NB * 64 * NPTS];
__device__ float g_bufB[NB * 128 * NPTS];
__device__ float g_y5[NB * 256 * NPTS];
__device__ float g_bn[5][2][256];
__device__ float g_stat[512];              // per-layer BN sum/sumsq accumulator
__device__ float g_r[NB * 256];            // per-batch channel raw sums of f
__device__ float g_Spart[4 * NB * 256 * 256];
__device__ float g_nrm[NB];
__device__ float g_Y[NB * 256 * 256];
__device__ float g_Z[NB * 256 * 256];
__device__ float g_P[NB * 256 * 256];
__device__ float g_Y2[NB * 256 * 256];
__device__ float g_Z2[NB * 256 * 256];
__device__ float g_part[16 * 256 * NB];

// ---------------- layer 0: 3 -> 64 raw, fused BN-stat accumulation ----------------
__global__ void k_layer0(const float* __restrict__ pts, const float* __restrict__ W0,
                         float* __restrict__ y, float* __restrict__ stat) {
    __shared__ float w[192];
    int t = threadIdx.x;
    if (t < 192) w[t] = W0[t];
    __syncthreads();
    int b = blockIdx.y;
    int n = blockIdx.x * 256 + t;
    bool valid = (n < NPTS);
    float p0 = 0.f, p1 = 0.f, p2 = 0.f;
    if (valid) {
        const float* p = pts + ((size_t)b * NPTS + n) * 3;
        p0 = p[0]; p1 = p[1]; p2 = p[2];
    }
    float* yo = y + (size_t)b * 64 * NPTS + n;
    int lane = t & 31;
#pragma unroll
    for (int o = 0; o < 64; ++o) {
        float v = w[o * 3] * p0 + w[o * 3 + 1] * p1 + w[o * 3 + 2] * p2;
        if (valid) yo[(size_t)o * NPTS] = v;
        float s = v, q = v * v;
#pragma unroll
        for (int m2 = 16; m2 >= 1; m2 >>= 1) {
            s += __shfl_xor_sync(0xffffffffu, s, m2);
            q += __shfl_xor_sync(0xffffffffu, q, m2);
        }
        if (lane == 0) { atomicAdd(&stat[o], s); atomicAdd(&stat[256 + o], q); }
    }
}

// ---------------- finalize BN scale/shift from accumulated sums ----------------
__global__ void k_bnfin(const float* __restrict__ stat, int C,
                        const float* __restrict__ gam, const float* __restrict__ bet,
                        float* __restrict__ bnout) {
    int t = threadIdx.x;
    if (t < C) {
        float inv = 1.f / (NB * (float)NPTS);
        float mu = stat[t] * inv;
        float var = stat[256 + t] * inv - mu * mu;
        float sc = gam[t] * rsqrtf(var + BN_EPS);
        bnout[t] = sc;
        bnout[256 + t] = bet[t] - mu * sc;
    }
}

// ---------------- y = W @ relu(bn(x)); tile 64o x 128n; fused stats ----------------
template <int CIN, int COUT>
__global__ void k_layer(const float* __restrict__ x, const float* __restrict__ W,
                        const float* __restrict__ bn, float* __restrict__ y,
                        float* __restrict__ stat) {
    const int b = blockIdx.y;
    const int n0 = blockIdx.x * 128;
    const int o0 = blockIdx.z * 64;
    __shared__ float xs[16][132];
    __shared__ float ws[16][65];
    const float* scale = bn;
    const float* shift = bn + 256;
    float acc[4][8];
#pragma unroll
    for (int i = 0; i < 4; i++)
#pragma unroll
        for (int j = 0; j < 8; j++) acc[i][j] = 0.f;
    int t = threadIdx.x, tx = t & 15, ty = t >> 4;
    for (int c0 = 0; c0 < CIN; c0 += 16) {
#pragma unroll
        for (int i = 0; i < 8; ++i) {
            int e = t + i * 256; int cc = e >> 7, nn = e & 127;
            int n = n0 + nn; int c = c0 + cc;
            float v = 0.f;
            if (n < NPTS) {
                v = x[((size_t)b * CIN + c) * NPTS + n];
                v = fmaxf(fmaf(v, scale[c], shift[c]), 0.f);
            }
            xs[cc][nn] = v;
        }
#pragma unroll
        for (int i = 0; i < 4; ++i) {
            int e = t + i * 256; int oo = e >> 4, cc = e & 15;
            ws[cc][oo] = W[(size_t)(o0 + oo) * CIN + (c0 + cc)];
        }
        __syncthreads();
#pragma unroll
        for (int cc = 0; cc < 16; ++cc) {
            float a[4];
#pragma unroll
            for (int i = 0; i < 4; i++) a[i] = ws[cc][ty * 4 + i];
            float4 b0 = *(const float4*)&xs[cc][tx * 8];
            float4 b1 = *(const float4*)&xs[cc][tx * 8 + 4];
            float bb[8] = {b0.x, b0.y, b0.z, b0.w, b1.x, b1.y, b1.z, b1.w};
#pragma unroll
            for (int i = 0; i < 4; i++)
#pragma unroll
                for (int j = 0; j < 8; j++) acc[i][j] = fmaf(a[i], bb[j], acc[i][j]);
        }
        __syncthreads();
    }
#pragma unroll
    for (int i = 0; i < 4; i++) {
        int o = o0 + ty * 4 + i;
        float* yp = y + ((size_t)b * COUT + o) * NPTS + n0 + tx * 8;
#pragma unroll
        for (int j = 0; j < 8; j++) {
            int n = n0 + tx * 8 + j;
            if (n < NPTS) yp[j] = acc[i][j];
        }
    }
    // fused BN-stat epilogue (padded n contribute exactly 0)
#pragma unroll
    for (int i = 0; i < 4; i++) {
        float s = 0.f, q = 0.f;
#pragma unroll
        for (int j = 0; j < 8; j++) { float v = acc[i][j]; s += v; q += v * v; }
#pragma unroll
        for (int m2 = 8; m2 >= 1; m2 >>= 1) {
            s += __shfl_xor_sync(0xffffffffu, s, m2);
            q += __shfl_xor_sync(0xffffffffu, q, m2);
        }
        if (tx == 0) {
            int o = o0 + ty * 4 + i;
            atomicAdd(&stat[o], s);
            atomicAdd(&stat[256 + o], q);
        }
    }
}

// ---------------- SYRK partials + fused per-batch channel sums ----------------
__global__ void k_syrk(const float* __restrict__ y5, const float* __restrict__ bn,
                       float* __restrict__ Sp, float* __restrict__ r) {
    const int b = blockIdx.y, ks = blockIdx.z;
    int ti, tj;
    if (blockIdx.x == 0)      { ti = 0; tj = 0; }
    else if (blockIdx.x == 1) { ti = 0; tj = 1; }
    else                      { ti = 1; tj = 1; }
    const int i0 = ti * 128, j0 = tj * 128;
    const int nstart = ks * 2500, nend = nstart + 2500;
    __shared__ float as[16][132];
    __shared__ float bs[16][132];
    const float* scale = bn;
    const float* shift = bn + 256;
    float acc[8][8];
#pragma unroll
    for (int i = 0; i < 8; i++)
#pragma unroll
        for (int j = 0; j < 8; j++) acc[i][j] = 0.f;
    float rs[8];
#pragma unroll
    for (int i = 0; i < 8; i++) rs[i] = 0.f;
    int t = threadIdx.x, tx = t & 15, ty = t >> 4;
    const bool diag = (ti == tj);
    for (int n0 = nstart; n0 < nend; n0 += 16) {
#pragma unroll
        for (int i = 0; i < 8; ++i) {
            int e = t + i * 256; int ii = e >> 4, kk = e & 15;
            int n = n0 + kk;
            float v = 0.f, v2 = 0.f;
            if (n < nend) {
                int c = i0 + ii;
                v = fmaxf(fmaf(y5[((size_t)b * 256 + c) * NPTS + n], scale[c], shift[c]), 0.f);
                int c2 = j0 + ii;
                v2 = fmaxf(fmaf(y5[((size_t)b * 256 + c2) * NPTS + n], scale[c2], shift[c2]), 0.f);
            }
            as[kk][ii] = v;
            bs[kk][ii] = v2;
            if (diag) rs[i] += v;
        }
        __syncthreads();
#pragma unroll
        for (int kk = 0; kk < 16; ++kk) {
            float4 a0 = *(const float4*)&as[kk][ty * 8];
            float4 a1 = *(const float4*)&as[kk][ty * 8 + 4];
            float4 c0 = *(const float4*)&bs[kk][tx * 8];
            float4 c1 = *(const float4*)&bs[kk][tx * 8 + 4];
            float a[8] = {a0.x, a0.y, a0.z, a0.w, a1.x, a1.y, a1.z, a1.w};
            float bb[8] = {c0.x, c0.y, c0.z, c0.w, c1.x, c1.y, c1.z, c1.w};
#pragma unroll
            for (int i = 0; i < 8; i++)
#pragma unroll
                for (int j = 0; j < 8; j++) acc[i][j] = fmaf(a[i], bb[j], acc[i][j]);
        }
        __syncthreads();
    }
    if (diag) {
#pragma unroll
        for (int i = 0; i < 8; i++) {
            float s = rs[i];
#pragma unroll
            for (int m2 = 8; m2 >= 1; m2 >>= 1) s += __shfl_xor_sync(0xffffffffu, s, m2);
            if (tx == 0) atomicAdd(&r[b * 256 + i0 + (t >> 4) + i * 16], s);
        }
    }
    float* Sb = Sp + ((size_t)ks * NB + b) * 65536;
#pragma unroll
    for (int i = 0; i < 8; i++)
#pragma unroll
        for (int j = 0; j < 8; j++) {
            int ii = i0 + ty * 8 + i, jj = j0 + tx * 8 + j;
            Sb[ii * 256 + jj] = acc[i][j];
            if (!diag) Sb[jj * 256 + ii] = acc[i][j];
        }
}

// ---------------- cov assembly + Frobenius norm + NS init (m computed inline) ----------------
__global__ void k_cov(const float* __restrict__ Sp, const float* __restrict__ r,
                      float* __restrict__ Y, float* __restrict__ Z,
                      float* __restrict__ nrm) {
    int b = blockIdx.x, t = threadIdx.x;
    const float invN = 1.f / (float)NPTS;
    __shared__ float ms[256], rbm[256];
    {
        float s = 0.f;
        for (int bb = 0; bb < NB; ++bb) s += r[bb * 256 + t];
        ms[t] = s / (NB * (float)NPTS);
        rbm[t] = r[b * 256 + t] * invN;
    }
    __syncthreads();
    float* Yb = Y + (size_t)b * 65536;
    float* Zb = Z + (size_t)b * 65536;
    float ssq = 0.f;
    for (int e = t; e < 65536; e += 256) {
        int i = e >> 8, j = e & 255;
        float s = 0.f;
        for (int ks = 0; ks < 4; ++ks) s += Sp[((size_t)ks * NB + b) * 65536 + e];
        float c = s * invN - rbm[i] * ms[j] - ms[i] * rbm[j] + ms[i] * ms[j];
        Yb[e] = c;
        ssq += c * c;
        Zb[e] = (i == j) ? 1.f : 0.f;
    }
    __shared__ float red[256];
    __shared__ float snorm;
    red[t] = ssq; __syncthreads();
    for (int st = 128; st > 0; st >>= 1) {
        if (t < st) red[t] += red[t + st];
        __syncthreads();
    }
    if (t == 0) { snorm = sqrtf(red[0]); nrm[b] = snorm; }
    __syncthreads();
    float inv = 1.f / snorm;
    for (int e = t; e < 65536; e += 256) Yb[e] *= inv;
}

// ---------------- batched 256^3 GEMM (tile 128x64), optional P-epilogue ----------------
__global__ void k_bgemm256(const float* __restrict__ A0, const float* __restrict__ B0,
                           float* __restrict__ C0, const float* __restrict__ A1,
                           const float* __restrict__ B1, float* __restrict__ C1,
                           float alpha, int epi) {
    const float* A = A0; const float* Bm = B0; float* C = C0;
    if (blockIdx.z == 1) { A = A1; Bm = B1; C = C1; }
    int b = blockIdx.y;
    A  += (size_t)b * 65536;
    Bm += (size_t)b * 65536;
    C  += (size_t)b * 65536;
    int i0 = (blockIdx.x >> 2) * 128, j0 = (blockIdx.x & 3) * 64;
    __shared__ float as[16][132];
    __shared__ float bsm[16][68];
    float acc[8][4];
#pragma unroll
    for (int i = 0; i < 8; i++)
#pragma unroll
        for (int j = 0; j < 4; j++) acc[i][j] = 0.f;
    int t = threadIdx.x, tx = t & 15, ty = t >> 4;
    for (int c0 = 0; c0 < 256; c0 += 16) {
#pragma unroll
        for (int i = 0; i < 8; ++i) {
            int e = t + i * 256; int ii = e >> 4, kk = e & 15;
            as[kk][ii] = A[(i0 + ii) * 256 + c0 + kk];
        }
#pragma unroll
        for (int i = 0; i < 4; ++i) {
            int e = t + i * 256; int kk = e >> 6, jj = e & 63;
            bsm[kk][jj] = Bm[(c0 + kk) * 256 + j0 + jj];
        }
        __syncthreads();
#pragma unroll
        for (int kk = 0; kk < 16; ++kk) {
            float4 a0 = *(const float4*)&as[kk][ty * 8];
            float4 a1 = *(const float4*)&as[kk][ty * 8 + 4];
            float4 bv = *(const float4*)&bsm[kk][tx * 4];
            float a[8] = {a0.x, a0.y, a0.z, a0.w, a1.x, a1.y, a1.z, a1.w};
            float bb[4] = {bv.x, bv.y, bv.z, bv.w};
#pragma unroll
            for (int i = 0; i < 8; i++)
#pragma unroll
                for (int j = 0; j < 4; j++) acc[i][j] = fmaf(a[i], bb[j], acc[i][j]);
        }
        __syncthreads();
    }
#pragma unroll
    for (int i = 0; i < 8; i++)
#pragma unroll
        for (int j = 0; j < 4; j++) {
            int ii = i0 + ty * 8 + i, jj = j0 + tx * 4 + j;
            float v = acc[i][j];
            if (epi) v = ((ii == jj) ? alpha : 0.f) - (alpha - 1.f) * v;
            C[ii * 256 + jj] = v;
        }
}

// ---------------- FC partials over 4096-k chunks ----------------
__global__ void k_fc(const float* __restrict__ Yfin, const float* __restrict__ nrm,
                     const float* __restrict__ Wfc, float* __restrict__ part) {
    int o0 = blockIdx.x * 16, k0 = blockIdx.y * 4096;
    __shared__ float vs[16][129];
    __shared__ float wsm[16][129];
    __shared__ float sq[16];
    int t = threadIdx.x;
    if (t < 16) sq[t] = sqrtf(nrm[t]);
    __syncthreads();
    int oo = t & 15, bb = t >> 4;
    float acc = 0.f;
    for (int kc = 0; kc < 4096; kc += 128) {
#pragma unroll
        for (int i = 0; i < 8; ++i) {
            int e = t + i * 256; int row = e >> 7, kk = e & 127;
            vs[row][kk]  = sq[row] * Yfin[(size_t)row * 65536 + k0 + kc + kk];
            wsm[row][kk] = Wfc[(size_t)(o0 + row) * 65536 + k0 + kc + kk];
        }
        __syncthreads();
#pragma unroll
        for (int kk = 0; kk < 128; kk++) acc = fmaf(wsm[oo][kk], vs[bb][kk], acc);
        __syncthreads();
    }
    part[((size_t)blockIdx.y * 256 + o0 + oo) * 16 + bb] = acc;
}

// ---------------- finalize: bias + L2 normalize ----------------
__global__ void k_fin(const float* __restrict__ part, const float* __restrict__ bfc,
                      float* __restrict__ out) {
    int b = blockIdx.x, t = threadIdx.x;
    float v = bfc[t];
    for (int ks = 0; ks < 16; ++ks) v += part[((size_t)ks * 256 + t) * 16 + b];
    __shared__ float red[256];
    red[t] = v * v; __syncthreads();
    for (int st = 128; st > 0; st >>= 1) {
        if (t < st) red[t] += red[t + st];
        __syncthreads();
    }
    float nrm = fmaxf(sqrtf(red[0]), 1e-12f);
    out[b * 256 + t] = v / nrm;
}

// ---------------- host driver ----------------
static float* symaddr(const void* sym) {
    void* p = nullptr;
    cudaGetSymbolAddress(&p, sym);
    return (float*)p;
}

extern "C" void kernel_launch(void* const* d_in, const int* in_sizes, int n_in,
                              void* d_out, int out_size) {
    const float* pts = (const float*)d_in[0];
    const float* W[5]; const float* G[5]; const float* Bt[5];
    for (int l = 0; l < 5; ++l) {
        W[l]  = (const float*)d_in[1 + 3 * l];
        G[l]  = (const float*)d_in[2 + 3 * l];
        Bt[l] = (const float*)d_in[3 + 3 * l];
    }
    const float* Wfc = (const float*)d_in[16];
    const float* bfc = (const float*)d_in[17];
    float* out = (float*)d_out;

    float* bufA = symaddr(g_bufA);
    float* bufB = symaddr(g_bufB);
    float* y5   = symaddr(g_y5);
    float* bn   = symaddr(g_bn);
    float* stat = symaddr(g_stat);
    float* r    = symaddr(g_r);
    float* Sp   = symaddr(g_Spart);
    float* nrm  = symaddr(g_nrm);
    float* Y    = symaddr(g_Y);
    float* Z    = symaddr(g_Z);
    float* P    = symaddr(g_P);
    float* Y2   = symaddr(g_Y2);
    float* Z2   = symaddr(g_Z2);
    float* part = symaddr(g_part);

    const int NT = (NPTS + 127) / 128;  // 79

    // MLP 3->64->64->64->128->256 with fused training-mode BN stats
    cudaMemsetAsync(stat, 0, 512 * sizeof(float), 0);
    k_layer0<<<dim3((NPTS + 255) / 256, NB), 256>>>(pts, W[0], bufA, stat);
    k_bnfin<<<1, 256>>>(stat, 64, G[0], Bt[0], bn + 0 * 512);

    cudaMemsetAsync(stat, 0, 512 * sizeof(float), 0);
    k_layer<64, 64><<<dim3(NT, NB, 1), 256>>>(bufA, W[1], bn + 0 * 512, bufB, stat);
    k_bnfin<<<1, 256>>>(stat, 64, G[1], Bt[1], bn + 1 * 512);

    cudaMemsetAsync(stat, 0, 512 * sizeof(float), 0);
    k_layer<64, 64><<<dim3(NT, NB, 1), 256>>>(bufB, W[2], bn + 1 * 512, bufA, stat);
    k_bnfin<<<1, 256>>>(stat, 64, G[2], Bt[2], bn + 2 * 512);

    cudaMemsetAsync(stat, 0, 512 * sizeof(float), 0);
    k_layer<64, 128><<<dim3(NT, NB, 2), 256>>>(bufA, W[3], bn + 2 * 512, bufB, stat);
    k_bnfin<<<1, 256>>>(stat, 128, G[3], Bt[3], bn + 3 * 512);

    cudaMemsetAsync(stat, 0, 512 * sizeof(float), 0);
    k_layer<128, 256><<<dim3(NT, NB, 4), 256>>>(bufB, W[4], bn + 3 * 512, y5, stat);
    k_bnfin<<<1, 256>>>(stat, 256, G[4], Bt[4], bn + 4 * 512);

    // second-order pooling (row sums fused into syrk)
    cudaMemsetAsync(r, 0, NB * 256 * sizeof(float), 0);
    k_syrk<<<dim3(3, NB, 4), 256>>>(y5, bn + 4 * 512, Sp, r);
    k_cov<<<NB, 256>>>(Sp, r, Y, Z, nrm);

    // coupled Newton-Schulz (full GEMM, proven stable): 16 accel + 6 standard
    float* curY = Y; float* curZ = Z; float* nY = Y2; float* nZ = Z2;
    for (int it = 0; it < 22; ++it) {
        float alpha = (it < 16) ? 1.9f : 1.5f;
        k_bgemm256<<<dim3(8, NB, 1), 256>>>(curZ, curY, P, curZ, curY, P, alpha, 1);
        k_bgemm256<<<dim3(8, NB, 2), 256>>>(curY, P, nY, P, curZ, nZ, 0.f, 0);
        float* tY = curY; curY = nY; nY = tY;
        float* tZ = curZ; curZ = nZ; nZ = tZ;
    }

    // FC + L2 normalize
    k_fc<<<dim3(16, 16), 256>>>(curY, nrm, Wfc, part);
    k_fin<<<NB, 256>>>(part, bfc, out);
}